// round 5
// baseline (speedup 1.0000x reference)
#include <cuda_runtime.h>
#include <cuda_bf16.h>
#include <cstdint>

#define TT   512
#define BB   128
#define DIN  64
#define NN   512
#define DOUT 2
#define GRID 96
#define NTHR 512

typedef __nv_bfloat16 bf16;

// ---------------- persistent device scratch ----------------
__device__ bf16   g_r_hi[2][3 * BB * NN];
__device__ bf16   g_r_lo[2][3 * BB * NN];
__device__ bf16   g_Wrec_hi[3][NN * NN];
__device__ bf16   g_Wrec_lo[3][NN * NN];
__device__ bf16   g_Wcross_hi[3][NN * NN];   // [0]=W_CA, [1]=W_AB, [2]=W_BC
__device__ bf16   g_Wcross_lo[3][NN * NN];
__device__ float  g_Xin[(size_t)TT * BB * NN];
__device__ float  g_hist[(size_t)(TT - 1) * BB * NN];
__device__ unsigned g_bar_count;
__device__ unsigned g_bar_gen;

// ---------------- small asm helpers ----------------
__device__ __forceinline__ uint32_t smaddr(const void* p) {
    return (uint32_t)__cvta_generic_to_shared(p);
}
__device__ __forceinline__ void cp_async16(void* s, const void* g) {
    asm volatile("cp.async.cg.shared.global [%0], [%1], 16;\n" :: "r"(smaddr(s)), "l"(g));
}
__device__ __forceinline__ void cp_commit() { asm volatile("cp.async.commit_group;\n"); }
__device__ __forceinline__ void cp_wait0()  { asm volatile("cp.async.wait_group 0;\n"); }
__device__ __forceinline__ void ldsm_x4(uint32_t r[4], uint32_t addr) {
    asm volatile("ldmatrix.sync.aligned.m8n8.x4.shared.b16 {%0,%1,%2,%3}, [%4];\n"
                 : "=r"(r[0]), "=r"(r[1]), "=r"(r[2]), "=r"(r[3]) : "r"(addr));
}
__device__ __forceinline__ void ldsm_x2(uint32_t r[2], uint32_t addr) {
    asm volatile("ldmatrix.sync.aligned.m8n8.x2.shared.b16 {%0,%1}, [%2];\n"
                 : "=r"(r[0]), "=r"(r[1]) : "r"(addr));
}
__device__ __forceinline__ void mma_bf16(float c[4], const uint32_t a[4], const uint32_t b[2]) {
    asm volatile(
        "mma.sync.aligned.m16n8k16.row.col.f32.bf16.bf16.f32 "
        "{%0,%1,%2,%3}, {%4,%5,%6,%7}, {%8,%9}, {%0,%1,%2,%3};\n"
        : "+f"(c[0]), "+f"(c[1]), "+f"(c[2]), "+f"(c[3])
        : "r"(a[0]), "r"(a[1]), "r"(a[2]), "r"(a[3]), "r"(b[0]), "r"(b[1]));
}

// swizzled smem offset (elements). tile row stride = 64 bf16 = 8 x 16B units.
__device__ __forceinline__ int swz(int row, int k) {
    return row * 64 + (((k >> 3) ^ (row & 7)) << 3) + (k & 7);
}

// ---------------- init ----------------
__global__ void init_zero() {
    int i = blockIdx.x * blockDim.x + threadIdx.x;
    if (i < 3 * BB * NN) {
        g_r_hi[0][i] = __float2bfloat16(0.f);
        g_r_lo[0][i] = __float2bfloat16(0.f);
    }
    if (i == 0) { g_bar_count = 0; g_bar_gen = 0; }
}

// ---------------- weight split fp32 -> bf16 hi/lo ----------------
__global__ void split_w(const float* a, const float* b, const float* c,
                        const float* ca, const float* ab, const float* bc) {
    int i = blockIdx.x * blockDim.x + threadIdx.x; // 6 * 262144
    int m = i >> 18;
    int j = i & 262143;
    const float* srcs[6] = {a, b, c, ca, ab, bc};
    float w = srcs[m][j];
    bf16 hi = __float2bfloat16(w);
    bf16 lo = __float2bfloat16(w - __bfloat162float(hi));
    if (m < 3) { g_Wrec_hi[m][j] = hi; g_Wrec_lo[m][j] = lo; }
    else       { g_Wcross_hi[m - 3][j] = hi; g_Wcross_lo[m - 3][j] = lo; }
}

// ---------------- precompute Xin = X @ W_in_A.T (fp32) ----------------
__global__ __launch_bounds__(256) void precompute_in(const float* X, const float* Win) {
    __shared__ float sX[64][68];
    __shared__ float sWt[64][72]; // transposed: [d][n]
    int rb = blockIdx.x * 64;
    int cb = blockIdx.y * 64;
    int tid = threadIdx.x;

    for (int v = tid; v < 1024; v += 256) {
        int row = v >> 4, d4 = (v & 15) * 4;
        float4 tx = *(const float4*)(X + (size_t)(rb + row) * DIN + d4);
        sX[row][d4 + 0] = tx.x; sX[row][d4 + 1] = tx.y;
        sX[row][d4 + 2] = tx.z; sX[row][d4 + 3] = tx.w;
    }
    for (int v = tid; v < 1024; v += 256) {
        int n = v >> 4, d4 = (v & 15) * 4;
        float4 tw = *(const float4*)(Win + (size_t)(cb + n) * DIN + d4);
        sWt[d4 + 0][n] = tw.x; sWt[d4 + 1][n] = tw.y;
        sWt[d4 + 2][n] = tw.z; sWt[d4 + 3][n] = tw.w;
    }
    __syncthreads();

    int ty = tid >> 4, tx = tid & 15;
    float acc[4][4];
#pragma unroll
    for (int i = 0; i < 4; i++)
#pragma unroll
        for (int j = 0; j < 4; j++) acc[i][j] = 0.f;

    for (int k = 0; k < 64; k++) {
        float a0 = sX[ty * 4 + 0][k], a1 = sX[ty * 4 + 1][k];
        float a2 = sX[ty * 4 + 2][k], a3 = sX[ty * 4 + 3][k];
        float4 bq = *(const float4*)&sWt[k][tx * 4];
        acc[0][0] += a0 * bq.x; acc[0][1] += a0 * bq.y; acc[0][2] += a0 * bq.z; acc[0][3] += a0 * bq.w;
        acc[1][0] += a1 * bq.x; acc[1][1] += a1 * bq.y; acc[1][2] += a1 * bq.z; acc[1][3] += a1 * bq.w;
        acc[2][0] += a2 * bq.x; acc[2][1] += a2 * bq.y; acc[2][2] += a2 * bq.z; acc[2][3] += a2 * bq.w;
        acc[3][0] += a3 * bq.x; acc[3][1] += a3 * bq.y; acc[3][2] += a3 * bq.z; acc[3][3] += a3 * bq.w;
    }
#pragma unroll
    for (int i = 0; i < 4; i++)
#pragma unroll
        for (int j = 0; j < 4; j++)
            g_Xin[(size_t)(rb + ty * 4 + i) * NN + cb + tx * 4 + j] = acc[i][j];
}

// ---------------- grid-wide barrier (all 96 CTAs co-resident) ----------------
__device__ __forceinline__ void grid_sync() {
    __syncthreads();
    if (threadIdx.x == 0) {
        volatile unsigned* vgen = &g_bar_gen;
        unsigned gen = *vgen;
        __threadfence();
        if (atomicAdd(&g_bar_count, 1u) == GRID - 1) {
            g_bar_count = 0;
            __threadfence();
            *vgen = gen + 1;
        } else {
            while (*vgen == gen) {}
        }
        __threadfence();
    }
    __syncthreads();
}

// ---------------- persistent fused RNN kernel ----------------
// grid = 96: region (3) x coltile (16) x rowtile (2). CTA tile = [64 rows x 32 cols].
// 512 threads = 16 warps (4 per SMSP) for latency hiding; warp tile = 16 rows x 8 cols.
// Weights resident in smem; leaky state x in registers.
// smem (bf16 elems):
//   W slots: 32 x 2048 at 0               (slot = (mat*8 + kc64)*2 + part), rows of 64 K
//   A slots: 8  x 4096 at 65536           (slot = (buf*2 + part)*2 + sub),  rows of 64 K
#define W_SLOT(mat, kc, part) ((((mat) * 8 + (kc)) * 2 + (part)) * 2048)
#define A_OFF 65536
#define A_SLOT(buf, part, sub) (A_OFF + (((buf) * 2 + (part)) * 2 + (sub)) * 4096)
#define SMEM_TOTAL ((A_OFF + 8 * 4096) * 2)   // bytes = 196608

// load one 128-K A chunk (hi+lo): 2048 16B units, 512 threads -> 4 cp.async each
__device__ __forceinline__ void load_A(const bf16* hi, const bf16* lo,
                                       int rb, int kb, bf16* sm, int buf, int tid) {
#pragma unroll
    for (int u = tid; u < 1024; u += NTHR) {
        int sub = u >> 9;                   // 0/1 : which 64-K subtile
        int w   = u & 511;
        int row = w >> 3, kk = (w & 7) << 3;
        int so  = swz(row, kk);
        const bf16* gh = hi + (size_t)(rb + row) * NN + kb + sub * 64 + kk;
        const bf16* gl = lo + (size_t)(rb + row) * NN + kb + sub * 64 + kk;
        cp_async16(sm + A_SLOT(buf, 0, sub) + so, gh);
        cp_async16(sm + A_SLOT(buf, 1, sub) + so, gl);
    }
}

__global__ __launch_bounds__(NTHR, 1) void persist_kernel() {
    extern __shared__ bf16 sm[];
    int tid  = threadIdx.x;
    int lane = tid & 31, warp = tid >> 5;
    int region = blockIdx.x >> 5;
    int rem    = blockIdx.x & 31;
    int ct = rem >> 1, rt = rem & 1;
    int rb = rt * 64, cb = ct * 32;
    int cross = (region + 2) % 3;          // A<-C, B<-A, C<-B
    int wr = warp & 3, wc = warp >> 2;     // wr: 4 row groups of 16; wc: 4 col groups of 8

    // ---- load resident weights into smem (once) ----
    for (int l = tid; l < 8192; l += NTHR) {
        int slot   = l >> 8;               // 0..31
        int within = l & 255;
        int row = within >> 3, kk = (within & 7) << 3;
        int part   = slot & 1;
        int kc     = (slot >> 1) & 7;
        int mat    = slot >> 4;
        const bf16* src =
            (mat == 0) ? (part ? g_Wrec_lo[region]   : g_Wrec_hi[region])
                       : (part ? g_Wcross_lo[region] : g_Wcross_hi[region]);
        cp_async16(sm + W_SLOT(mat, kc, part) + swz(row, kk),
                   src + (size_t)(cb + row) * NN + kc * 64 + kk);
    }
    cp_commit();
    cp_wait0();
    __syncthreads();

    // ---- persistent state in registers ----
    float xreg[4];
#pragma unroll
    for (int i = 0; i < 4; i++) xreg[i] = 0.f;

    // fragment addressing (constant across steps)
    int ar = wr * 16 + (lane & 15);
    int ak_off = (lane >> 4) << 3;
    int brow = wc * 8 + (lane & 7);
    int bk_off = ((lane >> 3) & 1) << 3;

    int g = lane >> 2, q = lane & 3;
    int row0 = rb + wr * 16 + g;
    int colb = cb + wc * 8 + q * 2;

    for (int t = 1; t < TT; t++) {
        int p_in = (t - 1) & 1, p_out = t & 1;
        const bf16* rhi[2] = { &g_r_hi[p_in][region * BB * NN], &g_r_hi[p_in][cross * BB * NN] };
        const bf16* rlo[2] = { &g_r_lo[p_in][region * BB * NN], &g_r_lo[p_in][cross * BB * NN] };

        float acc[4];
#pragma unroll
        for (int i = 0; i < 4; i++) acc[i] = 0.f;

        // prologue: chunk 0
        load_A(rhi[0], rlo[0], rb, 0, sm, 0, tid);
        cp_commit();

        for (int c = 0; c < 8; c++) {           // 8 chunks x 128 K
            int buf = c & 1;
            cp_wait0();                          // chunk c resident (this thread's parts)
            __syncthreads();                     // visible to all; prev mma done

            if (c < 7) {                         // prefetch chunk c+1
                int m2 = (c + 1) >> 2;
                int kb = ((c + 1) & 3) * 128;
                load_A(rhi[m2], rlo[m2], rb, kb, sm, buf ^ 1, tid);
                cp_commit();
            }

            int mat = c >> 2;
#pragma unroll
            for (int kk = 0; kk < 8; kk++) {
                int sub = kk >> 2;
                int ko  = (kk & 3) << 4;
                int kc  = (c & 3) * 2 + sub;    // 64-K index within matrix
                const bf16* Ah = sm + A_SLOT(buf, 0, sub);
                const bf16* Al = sm + A_SLOT(buf, 1, sub);
                const bf16* wh = sm + W_SLOT(mat, kc, 0);
                const bf16* wl = sm + W_SLOT(mat, kc, 1);
                uint32_t ah[4], al[4], bh[2], bl[2];
                ldsm_x4(ah, smaddr(Ah + swz(ar, ko + ak_off)));
                ldsm_x4(al, smaddr(Al + swz(ar, ko + ak_off)));
                ldsm_x2(bh, smaddr(wh + swz(brow, ko + bk_off)));
                ldsm_x2(bl, smaddr(wl + swz(brow, ko + bk_off)));
                mma_bf16(acc, ah, bh);
                mma_bf16(acc, ah, bl);
                mma_bf16(acc, al, bh);
            }
        }

        // ---- epilogue: leaky update + tanh + split-store rates ----
#pragma unroll
        for (int i2 = 0; i2 < 2; i2++) {
            int row = row0 + i2 * 8;
            int col = colb;
            float s0 = acc[i2 * 2 + 0];
            float s1 = acc[i2 * 2 + 1];
            if (region == 0) {
                float2 xin = *(const float2*)(g_Xin + (size_t)t * BB * NN + (size_t)row * NN + col);
                s0 += xin.x; s1 += xin.y;
            }
            float x0 = 0.9f * xreg[i2 * 2 + 0] + 0.1f * s0;
            float x1 = 0.9f * xreg[i2 * 2 + 1] + 0.1f * s1;
            xreg[i2 * 2 + 0] = x0;
            xreg[i2 * 2 + 1] = x1;
            float r0 = tanhf(x0), r1 = tanhf(x1);
            bf16 h0 = __float2bfloat16(r0);
            bf16 h1 = __float2bfloat16(r1);
            bf16 l0 = __float2bfloat16(r0 - __bfloat162float(h0));
            bf16 l1 = __float2bfloat16(r1 - __bfloat162float(h1));
            int idx = region * BB * NN + row * NN + col;
            *(__nv_bfloat162*)&g_r_hi[p_out][idx] = __nv_bfloat162(h0, h1);
            *(__nv_bfloat162*)&g_r_lo[p_out][idx] = __nv_bfloat162(l0, l1);
            if (region == 2)
                *(float2*)&g_hist[(size_t)(t - 1) * BB * NN + (size_t)row * NN + col] =
                    make_float2(r0, r1);
        }

        grid_sync();
    }
}

// ---------------- final readout: out = rC_hist @ W_out.T ----------------
__global__ void out_kernel(const float* Wout, float* out) {
    __shared__ float sw0[512], sw1[512];
    int bt = blockIdx.x;
    int tid = threadIdx.x; // 128 threads, one batch row each
    for (int j = tid; j < 512; j += 128) { sw0[j] = Wout[j]; sw1[j] = Wout[512 + j]; }
    __syncthreads();
    const float* row = g_hist + (size_t)bt * BB * NN + (size_t)tid * NN;
    float s0 = 0.f, s1 = 0.f;
    for (int j = 0; j < 512; j += 4) {
        float4 v = *(const float4*)(row + j);
        s0 += v.x * sw0[j] + v.y * sw0[j + 1] + v.z * sw0[j + 2] + v.w * sw0[j + 3];
        s1 += v.x * sw1[j] + v.y * sw1[j + 1] + v.z * sw1[j + 2] + v.w * sw1[j + 3];
    }
    out[((size_t)bt * BB + tid) * 2 + 0] = s0;
    out[((size_t)bt * BB + tid) * 2 + 1] = s1;
}

// ---------------- launch ----------------
extern "C" void kernel_launch(void* const* d_in, const int* in_sizes, int n_in,
                              void* d_out, int out_size) {
    const float* X     = (const float*)d_in[0];
    const float* WrecA = (const float*)d_in[1];
    const float* WrecB = (const float*)d_in[2];
    const float* WrecC = (const float*)d_in[3];
    const float* W_AB  = (const float*)d_in[4];
    const float* W_BC  = (const float*)d_in[5];
    const float* W_CA  = (const float*)d_in[6];
    const float* W_in  = (const float*)d_in[7];
    const float* W_out = (const float*)d_in[8];

    cudaFuncSetAttribute(persist_kernel, cudaFuncAttributeMaxDynamicSharedMemorySize, SMEM_TOTAL);

    init_zero<<<768, 256>>>();
    split_w<<<6144, 256>>>(WrecA, WrecB, WrecC, W_CA, W_AB, W_BC);
    dim3 pg(TT * BB / 64, NN / 64);
    precompute_in<<<pg, 256>>>(X, W_in);
    persist_kernel<<<GRID, NTHR, SMEM_TOTAL>>>();
    out_kernel<<<TT - 1, 128>>>(W_out, (float*)d_out);
}

// round 6
// speedup vs baseline: 1.5878x; 1.5878x over previous
#include <cuda_runtime.h>
#include <cuda_bf16.h>
#include <cstdint>

#define TT   512
#define BB   128
#define DIN  64
#define NN   512
#define DOUT 2
#define GRID 96
#define NTHR 128

typedef __nv_bfloat16 bf16;

// ---------------- persistent device scratch ----------------
__device__ bf16   g_r_hi[2][3 * BB * NN];
__device__ bf16   g_r_lo[2][3 * BB * NN];
__device__ bf16   g_Wrec_hi[3][NN * NN];
__device__ bf16   g_Wrec_lo[3][NN * NN];
__device__ bf16   g_Wcross_hi[3][NN * NN];   // [0]=W_CA, [1]=W_AB, [2]=W_BC
__device__ bf16   g_Wcross_lo[3][NN * NN];
__device__ float  g_Xin[(size_t)TT * BB * NN];
__device__ float  g_hist[(size_t)(TT - 1) * BB * NN];
__device__ unsigned g_bar_count;
__device__ unsigned g_bar_gen;

// ---------------- small asm helpers ----------------
__device__ __forceinline__ uint32_t smaddr(const void* p) {
    return (uint32_t)__cvta_generic_to_shared(p);
}
__device__ __forceinline__ void cp_async16(void* s, const void* g) {
    asm volatile("cp.async.cg.shared.global [%0], [%1], 16;\n" :: "r"(smaddr(s)), "l"(g));
}
__device__ __forceinline__ void cp_commit() { asm volatile("cp.async.commit_group;\n"); }
template<int N>
__device__ __forceinline__ void cp_wait() { asm volatile("cp.async.wait_group %0;\n" :: "n"(N)); }
__device__ __forceinline__ void ldsm_x4(uint32_t r[4], uint32_t addr) {
    asm volatile("ldmatrix.sync.aligned.m8n8.x4.shared.b16 {%0,%1,%2,%3}, [%4];\n"
                 : "=r"(r[0]), "=r"(r[1]), "=r"(r[2]), "=r"(r[3]) : "r"(addr));
}
__device__ __forceinline__ void mma_bf16(float c[4], const uint32_t a[4], const uint32_t b[2]) {
    asm volatile(
        "mma.sync.aligned.m16n8k16.row.col.f32.bf16.bf16.f32 "
        "{%0,%1,%2,%3}, {%4,%5,%6,%7}, {%8,%9}, {%0,%1,%2,%3};\n"
        : "+f"(c[0]), "+f"(c[1]), "+f"(c[2]), "+f"(c[3])
        : "r"(a[0]), "r"(a[1]), "r"(a[2]), "r"(a[3]), "r"(b[0]), "r"(b[1]));
}

// swizzled smem offset (elements). tile row stride = 64 bf16 = 8 x 16B units.
__device__ __forceinline__ int swz(int row, int k) {
    return row * 64 + (((k >> 3) ^ (row & 7)) << 3) + (k & 7);
}

// ---------------- init ----------------
__global__ void init_zero() {
    int i = blockIdx.x * blockDim.x + threadIdx.x;
    if (i < 3 * BB * NN) {
        g_r_hi[0][i] = __float2bfloat16(0.f);
        g_r_lo[0][i] = __float2bfloat16(0.f);
    }
    if (i == 0) { g_bar_count = 0; g_bar_gen = 0; }
}

// ---------------- weight split fp32 -> bf16 hi/lo ----------------
__global__ void split_w(const float* a, const float* b, const float* c,
                        const float* ca, const float* ab, const float* bc) {
    int i = blockIdx.x * blockDim.x + threadIdx.x; // 6 * 262144
    int m = i >> 18;
    int j = i & 262143;
    const float* srcs[6] = {a, b, c, ca, ab, bc};
    float w = srcs[m][j];
    bf16 hi = __float2bfloat16(w);
    bf16 lo = __float2bfloat16(w - __bfloat162float(hi));
    if (m < 3) { g_Wrec_hi[m][j] = hi; g_Wrec_lo[m][j] = lo; }
    else       { g_Wcross_hi[m - 3][j] = hi; g_Wcross_lo[m - 3][j] = lo; }
}

// ---------------- precompute Xin = X @ W_in_A.T (fp32) ----------------
__global__ __launch_bounds__(256) void precompute_in(const float* X, const float* Win) {
    __shared__ float sX[64][68];
    __shared__ float sWt[64][72]; // transposed: [d][n]
    int rb = blockIdx.x * 64;
    int cb = blockIdx.y * 64;
    int tid = threadIdx.x;

    for (int v = tid; v < 1024; v += 256) {
        int row = v >> 4, d4 = (v & 15) * 4;
        float4 tx = *(const float4*)(X + (size_t)(rb + row) * DIN + d4);
        sX[row][d4 + 0] = tx.x; sX[row][d4 + 1] = tx.y;
        sX[row][d4 + 2] = tx.z; sX[row][d4 + 3] = tx.w;
    }
    for (int v = tid; v < 1024; v += 256) {
        int n = v >> 4, d4 = (v & 15) * 4;
        float4 tw = *(const float4*)(Win + (size_t)(cb + n) * DIN + d4);
        sWt[d4 + 0][n] = tw.x; sWt[d4 + 1][n] = tw.y;
        sWt[d4 + 2][n] = tw.z; sWt[d4 + 3][n] = tw.w;
    }
    __syncthreads();

    int ty = tid >> 4, tx = tid & 15;
    float acc[4][4];
#pragma unroll
    for (int i = 0; i < 4; i++)
#pragma unroll
        for (int j = 0; j < 4; j++) acc[i][j] = 0.f;

    for (int k = 0; k < 64; k++) {
        float a0 = sX[ty * 4 + 0][k], a1 = sX[ty * 4 + 1][k];
        float a2 = sX[ty * 4 + 2][k], a3 = sX[ty * 4 + 3][k];
        float4 bq = *(const float4*)&sWt[k][tx * 4];
        acc[0][0] += a0 * bq.x; acc[0][1] += a0 * bq.y; acc[0][2] += a0 * bq.z; acc[0][3] += a0 * bq.w;
        acc[1][0] += a1 * bq.x; acc[1][1] += a1 * bq.y; acc[1][2] += a1 * bq.z; acc[1][3] += a1 * bq.w;
        acc[2][0] += a2 * bq.x; acc[2][1] += a2 * bq.y; acc[2][2] += a2 * bq.z; acc[2][3] += a2 * bq.w;
        acc[3][0] += a3 * bq.x; acc[3][1] += a3 * bq.y; acc[3][2] += a3 * bq.z; acc[3][3] += a3 * bq.w;
    }
#pragma unroll
    for (int i = 0; i < 4; i++)
#pragma unroll
        for (int j = 0; j < 4; j++)
            g_Xin[(size_t)(rb + ty * 4 + i) * NN + cb + tx * 4 + j] = acc[i][j];
}

// ---------------- grid-wide barrier (all 96 CTAs co-resident) ----------------
__device__ __forceinline__ void grid_sync() {
    __syncthreads();
    if (threadIdx.x == 0) {
        volatile unsigned* vgen = &g_bar_gen;
        unsigned gen = *vgen;
        __threadfence();
        if (atomicAdd(&g_bar_count, 1u) == GRID - 1) {
            g_bar_count = 0;
            __threadfence();
            *vgen = gen + 1;
        } else {
            while (*vgen == gen) {}
        }
        __threadfence();
    }
    __syncthreads();
}

// ---------------- persistent fused RNN kernel ----------------
// grid = 96: region (3) x coltile (16) x rowtile (2). CTA tile = [64 rows x 32 cols].
// 128 threads = 4 warps. Each warp owns a complete 16-row x 32-col output tile:
// loads its OWN 16 A-rows via cp.async (per-warp pipeline, NO __syncthreads in
// the chunk loop), reads resident weights, accumulates, epilogue. One grid
// barrier per step.
// smem (bf16 elems):
//   W slots: 32 x 2048 at 0      (slot = (mat*8+kc64)*2+part), 32 rows x 64 K
//   A bufs : 3 x 4 x 4096 at 65536  (buf, part*2+sub), 64 rows x 64 K
#define W_SLOT(mat, kc, part) ((((mat) * 8 + (kc)) * 2 + (part)) * 2048)
#define A_OFF 65536
#define A_SLOT(buf, part, sub) (A_OFF + ((buf) * 4 + (part) * 2 + (sub)) * 4096)
#define SMEM_TOTAL ((A_OFF + 12 * 4096) * 2)   // bytes = 229376

// warp loads its own 16 rows of one 128-K chunk (hi+lo): 512 16B units / 32 lanes
__device__ __forceinline__ void load_A_warp(const bf16* hi, const bf16* lo,
                                            int rb, int wr, int kb, bf16* sm,
                                            int buf, int lane) {
#pragma unroll
    for (int u = lane; u < 512; u += 32) {
        int part = u >> 8;                  // 0:hi 1:lo
        int rest = u & 255;
        int sub  = rest >> 7;               // 0/1 : 64-K subtile
        int w    = rest & 127;
        int row  = w >> 3, kk = (w & 7) << 3;
        const bf16* src = (part ? lo : hi) +
            (size_t)(rb + wr * 16 + row) * NN + kb + sub * 64 + kk;
        cp_async16(sm + A_SLOT(buf, part, sub) + swz(wr * 16 + row, kk), src);
    }
}

__global__ __launch_bounds__(NTHR, 1) void persist_kernel() {
    extern __shared__ bf16 sm[];
    int tid  = threadIdx.x;
    int lane = tid & 31, warp = tid >> 5;   // 4 warps
    int region = blockIdx.x >> 5;
    int rem    = blockIdx.x & 31;
    int ct = rem >> 1, rt = rem & 1;
    int rb = rt * 64, cb = ct * 32;
    int cross = (region + 2) % 3;          // A<-C, B<-A, C<-B
    int wr = warp;                          // warp owns rows wr*16..+16, all 32 cols

    // ---- load resident weights into smem (once) ----
    for (int l = tid; l < 8192; l += NTHR) {
        int slot   = l >> 8;               // 0..31
        int within = l & 255;
        int row = within >> 3, kk = (within & 7) << 3;
        int part   = slot & 1;
        int kc     = (slot >> 1) & 7;
        int mat    = slot >> 4;
        const bf16* src =
            (mat == 0) ? (part ? g_Wrec_lo[region]   : g_Wrec_hi[region])
                       : (part ? g_Wcross_lo[region] : g_Wcross_hi[region]);
        cp_async16(sm + W_SLOT(mat, kc, part) + swz(row, kk),
                   src + (size_t)(cb + row) * NN + kc * 64 + kk);
    }
    cp_commit();
    cp_wait<0>();
    __syncthreads();

    // ---- persistent leaky state in registers (16 outputs per thread) ----
    float xreg[16];
#pragma unroll
    for (int i = 0; i < 16; i++) xreg[i] = 0.f;

    // fragment addressing (constant across steps)
    int ar = wr * 16 + (lane & 15);
    int ak_off = (lane >> 4) << 3;
    int brow0 = ((lane >> 4) << 3) + (lane & 7);   // n 0-15 block
    int bk_off = ((lane >> 3) & 1) << 3;

    int g = lane >> 2, q = lane & 3;
    int row0 = rb + wr * 16 + g;                   // batch row (and +8)

    for (int t = 1; t < TT; t++) {
        int p_in = (t - 1) & 1, p_out = t & 1;
        const bf16* rhi[2] = { &g_r_hi[p_in][region * BB * NN], &g_r_hi[p_in][cross * BB * NN] };
        const bf16* rlo[2] = { &g_r_lo[p_in][region * BB * NN], &g_r_lo[p_in][cross * BB * NN] };

        // prefetch Xin for this step (region 0) — overlaps with mma loop
        float xin[16];
        if (region == 0) {
            const float* xp = g_Xin + (size_t)t * BB * NN;
#pragma unroll
            for (int nh = 0; nh < 4; nh++)
#pragma unroll
                for (int i2 = 0; i2 < 2; i2++) {
                    float2 v = *(const float2*)(xp + (size_t)(row0 + i2 * 8) * NN
                                                + cb + nh * 8 + q * 2);
                    xin[nh * 4 + i2 * 2 + 0] = v.x;
                    xin[nh * 4 + i2 * 2 + 1] = v.y;
                }
        }

        float acc[4][4];
#pragma unroll
        for (int nh = 0; nh < 4; nh++)
#pragma unroll
            for (int i = 0; i < 4; i++) acc[nh][i] = 0.f;

        // prologue: 3-deep per-warp pipeline (chunks 0,1,2)
        load_A_warp(rhi[0], rlo[0], rb, wr, 0, sm, 0, lane);   cp_commit();
        load_A_warp(rhi[0], rlo[0], rb, wr, 128, sm, 1, lane); cp_commit();
        load_A_warp(rhi[0], rlo[0], rb, wr, 256, sm, 2, lane); cp_commit();

        int buf = 0;
        for (int c = 0; c < 8; c++) {           // 8 chunks x 128 K
            cp_wait<2>();                        // chunk c landed (own warp's groups)
            __syncwarp();

            int mat = c >> 2;
#pragma unroll
            for (int sub = 0; sub < 2; sub++) {
                int kc = (c & 3) * 2 + sub;
                const bf16* Ah = sm + A_SLOT(buf, 0, sub);
                const bf16* Al = sm + A_SLOT(buf, 1, sub);
                const bf16* wh = sm + W_SLOT(mat, kc, 0);
                const bf16* wl = sm + W_SLOT(mat, kc, 1);
#pragma unroll
                for (int k16 = 0; k16 < 4; k16++) {
                    int ko = k16 << 4;
                    uint32_t ah[4], al[4], bh0[4], bh1[4], bl0[4], bl1[4];
                    ldsm_x4(ah,  smaddr(Ah + swz(ar, ko + ak_off)));
                    ldsm_x4(al,  smaddr(Al + swz(ar, ko + ak_off)));
                    ldsm_x4(bh0, smaddr(wh + swz(brow0,      ko + bk_off)));
                    ldsm_x4(bh1, smaddr(wh + swz(brow0 + 16, ko + bk_off)));
                    ldsm_x4(bl0, smaddr(wl + swz(brow0,      ko + bk_off)));
                    ldsm_x4(bl1, smaddr(wl + swz(brow0 + 16, ko + bk_off)));
                    mma_bf16(acc[0], ah, bh0 + 0);
                    mma_bf16(acc[1], ah, bh0 + 2);
                    mma_bf16(acc[2], ah, bh1 + 0);
                    mma_bf16(acc[3], ah, bh1 + 2);
                    mma_bf16(acc[0], ah, bl0 + 0);
                    mma_bf16(acc[1], ah, bl0 + 2);
                    mma_bf16(acc[2], ah, bl1 + 0);
                    mma_bf16(acc[3], ah, bl1 + 2);
                    mma_bf16(acc[0], al, bh0 + 0);
                    mma_bf16(acc[1], al, bh0 + 2);
                    mma_bf16(acc[2], al, bh1 + 0);
                    mma_bf16(acc[3], al, bh1 + 2);
                }
            }

            if (c < 5) {                         // keep pipeline 3 deep
                int c3 = c + 3;
                int m2 = c3 >> 2;
                int kb = (c3 & 3) * 128;
                load_A_warp(rhi[m2], rlo[m2], rb, wr, kb, sm, buf, lane);
                cp_commit();
            }
            if (++buf == 3) buf = 0;
        }

        // ---- epilogue: leaky update + tanh + split-store rates ----
#pragma unroll
        for (int nh = 0; nh < 4; nh++) {
#pragma unroll
            for (int i2 = 0; i2 < 2; i2++) {
                int row = row0 + i2 * 8;
                int col = cb + nh * 8 + q * 2;
                float s0 = acc[nh][i2 * 2 + 0];
                float s1 = acc[nh][i2 * 2 + 1];
                if (region == 0) {
                    s0 += xin[nh * 4 + i2 * 2 + 0];
                    s1 += xin[nh * 4 + i2 * 2 + 1];
                }
                int xi = nh * 4 + i2 * 2;
                float x0 = 0.9f * xreg[xi + 0] + 0.1f * s0;
                float x1 = 0.9f * xreg[xi + 1] + 0.1f * s1;
                xreg[xi + 0] = x0;
                xreg[xi + 1] = x1;
                float r0 = tanhf(x0), r1 = tanhf(x1);
                bf16 h0 = __float2bfloat16(r0);
                bf16 h1 = __float2bfloat16(r1);
                bf16 l0 = __float2bfloat16(r0 - __bfloat162float(h0));
                bf16 l1 = __float2bfloat16(r1 - __bfloat162float(h1));
                int idx = region * BB * NN + row * NN + col;
                *(__nv_bfloat162*)&g_r_hi[p_out][idx] = __nv_bfloat162(h0, h1);
                *(__nv_bfloat162*)&g_r_lo[p_out][idx] = __nv_bfloat162(l0, l1);
                if (region == 2)
                    *(float2*)&g_hist[(size_t)(t - 1) * BB * NN + (size_t)row * NN + col] =
                        make_float2(r0, r1);
            }
        }

        grid_sync();
    }
}

// ---------------- final readout: out = rC_hist @ W_out.T ----------------
__global__ void out_kernel(const float* Wout, float* out) {
    __shared__ float sw0[512], sw1[512];
    int bt = blockIdx.x;
    int tid = threadIdx.x; // 128 threads, one batch row each
    for (int j = tid; j < 512; j += 128) { sw0[j] = Wout[j]; sw1[j] = Wout[512 + j]; }
    __syncthreads();
    const float* row = g_hist + (size_t)bt * BB * NN + (size_t)tid * NN;
    float s0 = 0.f, s1 = 0.f;
    for (int j = 0; j < 512; j += 4) {
        float4 v = *(const float4*)(row + j);
        s0 += v.x * sw0[j] + v.y * sw0[j + 1] + v.z * sw0[j + 2] + v.w * sw0[j + 3];
        s1 += v.x * sw1[j] + v.y * sw1[j + 1] + v.z * sw1[j + 2] + v.w * sw1[j + 3];
    }
    out[((size_t)bt * BB + tid) * 2 + 0] = s0;
    out[((size_t)bt * BB + tid) * 2 + 1] = s1;
}

// ---------------- launch ----------------
extern "C" void kernel_launch(void* const* d_in, const int* in_sizes, int n_in,
                              void* d_out, int out_size) {
    const float* X     = (const float*)d_in[0];
    const float* WrecA = (const float*)d_in[1];
    const float* WrecB = (const float*)d_in[2];
    const float* WrecC = (const float*)d_in[3];
    const float* W_AB  = (const float*)d_in[4];
    const float* W_BC  = (const float*)d_in[5];
    const float* W_CA  = (const float*)d_in[6];
    const float* W_in  = (const float*)d_in[7];
    const float* W_out = (const float*)d_in[8];

    cudaFuncSetAttribute(persist_kernel, cudaFuncAttributeMaxDynamicSharedMemorySize, SMEM_TOTAL);

    init_zero<<<768, 256>>>();
    split_w<<<6144, 256>>>(WrecA, WrecB, WrecC, W_CA, W_AB, W_BC);
    dim3 pg(TT * BB / 64, NN / 64);
    precompute_in<<<pg, 256>>>(X, W_in);
    persist_kernel<<<GRID, NTHR, SMEM_TOTAL>>>();
    out_kernel<<<TT - 1, 128>>>(W_out, (float*)d_out);
}